// round 12
// baseline (speedup 1.0000x reference)
#include <cuda_runtime.h>
#include <cuda_fp16.h>
#include <cstdint>

#define DIM_K 512
#define NROWS 16384
#define MROWS 4096

// Scratch (no cudaMalloc allowed)
__device__ float g_xsq[NROWS];
__device__ float g_csq[MROWS];
__device__ __half g_Ah[(size_t)NROWS * DIM_K];
__device__ __half g_Bh[(size_t)MROWS * DIM_K];

// ---------------------------------------------------------------------------
// Fused convert(fp32->fp16) + row-norm kernel for BOTH matrices.
// One warp per row: 32 lanes x 4 float4 = 512 floats. Warp-reduce norm.
// ---------------------------------------------------------------------------
__global__ __launch_bounds__(256)
void conv_kernel(const float* __restrict__ A, const float* __restrict__ B,
                 int N, int M) {
    const int warp = (blockIdx.x * blockDim.x + threadIdx.x) >> 5;
    const int lane = threadIdx.x & 31;
    if (warp >= N + M) return;

    const float* src;
    __half2* dst;
    float* nrm;
    if (warp < N) {
        src = A + (size_t)warp * DIM_K;
        dst = reinterpret_cast<__half2*>(g_Ah + (size_t)warp * DIM_K);
        nrm = &g_xsq[warp];
    } else {
        const int row = warp - N;
        src = B + (size_t)row * DIM_K;
        dst = reinterpret_cast<__half2*>(g_Bh + (size_t)row * DIM_K);
        nrm = &g_csq[row];
    }

    float s = 0.0f;
    #pragma unroll
    for (int i = 0; i < 4; i++) {
        float4 v = reinterpret_cast<const float4*>(src)[lane + i * 32];
        dst[2 * (lane + i * 32) + 0] = __floats2half2_rn(v.x, v.y);
        dst[2 * (lane + i * 32) + 1] = __floats2half2_rn(v.z, v.w);
        s += v.x * v.x + v.y * v.y + v.z * v.z + v.w * v.w;
    }
    #pragma unroll
    for (int off = 16; off > 0; off >>= 1)
        s += __shfl_down_sync(0xffffffffu, s, off);
    if (lane == 0) *nrm = s;
}

// ---------------------------------------------------------------------------
// Legacy tensor-core helpers (base-target PTX: ldmatrix + mma.sync + cp.async)
// ---------------------------------------------------------------------------
__device__ __forceinline__ uint32_t smem_u32(const void* p) {
    uint32_t a;
    asm("{ .reg .u64 t; cvta.to.shared.u64 t, %1; cvt.u32.u64 %0, t; }"
        : "=r"(a) : "l"(p));
    return a;
}

__device__ __forceinline__ void cp_async16(uint32_t dst, const void* src) {
    asm volatile("cp.async.cg.shared.global [%0], [%1], 16;"
                 :: "r"(dst), "l"(src) : "memory");
}

__device__ __forceinline__ void ldsm_x4(uint32_t* r, uint32_t addr) {
    asm volatile("ldmatrix.sync.aligned.m8n8.x4.shared.b16 {%0,%1,%2,%3}, [%4];"
                 : "=r"(r[0]), "=r"(r[1]), "=r"(r[2]), "=r"(r[3]) : "r"(addr));
}

// fp16-accumulator HMMA: D,C are 2 x u32 (4 halves)
__device__ __forceinline__ void mma16816_h(uint32_t* d, const uint32_t* a,
                                           const uint32_t b0, const uint32_t b1) {
    asm volatile(
        "mma.sync.aligned.m16n8k16.row.col.f16.f16.f16.f16 "
        "{%0,%1}, {%2,%3,%4,%5}, {%6,%7}, {%0,%1};"
        : "+r"(d[0]), "+r"(d[1])
        : "r"(a[0]), "r"(a[1]), "r"(a[2]), "r"(a[3]), "r"(b0), "r"(b1));
}

// streaming store (bypass-ish L2 policy hint)
__device__ __forceinline__ void stcs_f2(float* p, float2 v) {
    asm volatile("st.global.cs.v2.f32 [%0], {%1, %2};"
                 :: "l"(p), "f"(v.x), "f"(v.y) : "memory");
}

// SW128 on 128B rows, relative offsets
__device__ __forceinline__ uint32_t swz(int r, int cb) {
    return (uint32_t)(r * 128 + (cb ^ ((r & 7) << 4)));
}

// ---------------------------------------------------------------------------
// GEMM: CTA 128x256, BK=64 halves, 4 stages, 16 warps (warp tile 32x64).
// out[n][m] = xsq[n] + csq[m] - 2 * dot(A[n,:], B[m,:])
// ---------------------------------------------------------------------------
#define BM 128
#define BN 256
#define BK 64                       // halves -> 128 B per smem row
#define NS (DIM_K / BK)             // 8
#define STAGES 4
#define NTHREADS 512
#define A_BYTES (BM * 128)          // 16 KB
#define B_BYTES (BN * 128)          // 32 KB
#define STAGE_BYTES (A_BYTES + B_BYTES)
#define DYN_SMEM (STAGES * STAGE_BYTES + 1024)

__global__ __launch_bounds__(NTHREADS, 1)
void dist_hmma_kernel(float* __restrict__ C, int M) {
    extern __shared__ char dyn[];
    uint32_t base = (smem_u32(dyn) + 1023u) & ~1023u;

    const int tid  = threadIdx.x;
    const int wid  = tid >> 5;
    const int lane = tid & 31;
    const int rowBase = blockIdx.y * BM;
    const int colBase = blockIdx.x * BN;
    const int wm = (wid & 3) * 32;        // warp row offset in tile (4 rows)
    const int wn = (wid >> 2) * 64;       // warp col offset in tile (4 cols)

    const __half* gA = g_Ah + (size_t)rowBase * DIM_K;
    const __half* gB = g_Bh + (size_t)colBase * DIM_K;

    uint32_t acc[2][8][2];                // f16x2 accumulators
    #pragma unroll
    for (int i = 0; i < 2; i++)
        #pragma unroll
        for (int j = 0; j < 8; j++) {
            acc[i][j][0] = 0u;
            acc[i][j][1] = 0u;
        }

    // ---- loader: 512 threads, A: 2 chunks, B: 4 chunks (16B each) ----
    auto load_stage = [&](int ks) {
        const int s = ks & (STAGES - 1);
        const uint32_t sA = base + s * STAGE_BYTES;
        const uint32_t sB = sA + A_BYTES;
        const __half* srcA = gA + ks * BK;
        const __half* srcB = gB + ks * BK;
        #pragma unroll
        for (int i = 0; i < 2; i++) {
            int idx = tid + i * NTHREADS;       // 0..1023
            int r = idx >> 3, q = idx & 7;
            cp_async16(sA + swz(r, q * 16), srcA + (size_t)r * DIM_K + q * 8);
        }
        #pragma unroll
        for (int i = 0; i < 4; i++) {
            int idx = tid + i * NTHREADS;       // 0..2047
            int r = idx >> 3, q = idx & 7;
            cp_async16(sB + swz(r, q * 16), srcB + (size_t)r * DIM_K + q * 8);
        }
    };

    #pragma unroll
    for (int s = 0; s < STAGES - 1; s++) {
        load_stage(s);
        asm volatile("cp.async.commit_group;" ::: "memory");
    }

    // per-lane fragment row/col components
    const int fr = (lane & 7) + ((lane >> 3) & 1) * 8;   // row within 16-tile
    const int fc = (lane >> 4) * 16;                     // byte col offset (k8 half)

    for (int ks = 0; ks < NS; ks++) {
        if (ks + STAGES - 1 < NS) load_stage(ks + STAGES - 1);
        asm volatile("cp.async.commit_group;" ::: "memory");
        asm volatile("cp.async.wait_group %0;" :: "n"(STAGES - 1) : "memory");
        __syncthreads();

        const int s = ks & (STAGES - 1);
        const uint32_t sA = base + s * STAGE_BYTES;
        const uint32_t sB = sA + A_BYTES;

        #pragma unroll
        for (int kk = 0; kk < 4; kk++) {      // 4 x k16 per BK=64
            const int cb = kk * 32 + fc;      // byte col in 128B row
            uint32_t aF[2][4], bR[4][4];
            #pragma unroll
            for (int mi = 0; mi < 2; mi++) {
                int r = wm + mi * 16 + fr;
                ldsm_x4(aF[mi], sA + swz(r, cb));
            }
            #pragma unroll
            for (int j = 0; j < 4; j++) {
                int r = wn + j * 16 + fr;
                ldsm_x4(bR[j], sB + swz(r, cb));
            }
            #pragma unroll
            for (int mi = 0; mi < 2; mi++) {
                #pragma unroll
                for (int j = 0; j < 4; j++) {
                    mma16816_h(acc[mi][2 * j + 0], aF[mi], bR[j][0], bR[j][2]);
                    mma16816_h(acc[mi][2 * j + 1], aF[mi], bR[j][1], bR[j][3]);
                }
            }
        }
        __syncthreads();
    }

    // ---- epilogue: out = xsq + csq - 2*dot, streaming float2 stores ----
    #pragma unroll
    for (int mi = 0; mi < 2; mi++) {
        const int row0 = rowBase + wm + mi * 16 + (lane >> 2);
        const float xs0 = g_xsq[row0];
        const float xs1 = g_xsq[row0 + 8];
        #pragma unroll
        for (int nj = 0; nj < 8; nj++) {
            const int col0 = colBase + wn + nj * 8 + (lane & 3) * 2;
            const float2 cs = *reinterpret_cast<const float2*>(&g_csq[col0]);
            float2 d0 = __half22float2(*reinterpret_cast<__half2*>(&acc[mi][nj][0]));
            float2 d1 = __half22float2(*reinterpret_cast<__half2*>(&acc[mi][nj][1]));
            float2 o0, o1;
            o0.x = xs0 + cs.x - 2.0f * d0.x;
            o0.y = xs0 + cs.y - 2.0f * d0.y;
            o1.x = xs1 + cs.x - 2.0f * d1.x;
            o1.y = xs1 + cs.y - 2.0f * d1.y;
            stcs_f2(C + (size_t)row0 * M + col0, o0);
            stcs_f2(C + (size_t)(row0 + 8) * M + col0, o1);
        }
    }
}

// ---------------------------------------------------------------------------
extern "C" void kernel_launch(void* const* d_in, const int* in_sizes, int n_in,
                              void* d_out, int out_size) {
    const float* A = (const float*)d_in[0];   // input   [N, 512]
    const float* B = (const float*)d_in[1];   // centres [M, 512]
    float* C = (float*)d_out;                 // [N, M]

    int N = in_sizes[0] / DIM_K;              // 16384
    int M = in_sizes[1] / DIM_K;              // 4096

    cudaFuncSetAttribute(dist_hmma_kernel,
                         cudaFuncAttributeMaxDynamicSharedMemorySize, DYN_SMEM);

    // One fused conversion kernel: one warp per row, N+M rows total.
    int totalWarps = N + M;                   // 20480
    int blocks = (totalWarps * 32 + 255) / 256;
    conv_kernel<<<blocks, 256>>>(A, B, N, M);

    dim3 grid(M / BN, N / BM);                // (16, 128)
    dist_hmma_kernel<<<grid, NTHREADS, DYN_SMEM>>>(C, M);
}

// round 13
// speedup vs baseline: 1.4575x; 1.4575x over previous
#include <cuda_runtime.h>
#include <cuda_fp16.h>
#include <cstdint>

#define DIM_K 512
#define NROWS 16384
#define MROWS 4096

// Scratch (no cudaMalloc allowed)
__device__ float g_xsq[NROWS];
__device__ float g_csq[MROWS];
__device__ __half g_Ah[(size_t)NROWS * DIM_K];
__device__ __half g_Bh[(size_t)MROWS * DIM_K];

// ---------------------------------------------------------------------------
// Fused convert(fp32->fp16) + row-norm kernel for BOTH matrices.
// ---------------------------------------------------------------------------
__global__ __launch_bounds__(256)
void conv_kernel(const float* __restrict__ A, const float* __restrict__ B,
                 int N, int M) {
    const int warp = (blockIdx.x * blockDim.x + threadIdx.x) >> 5;
    const int lane = threadIdx.x & 31;
    if (warp >= N + M) return;

    const float* src;
    __half2* dst;
    float* nrm;
    if (warp < N) {
        src = A + (size_t)warp * DIM_K;
        dst = reinterpret_cast<__half2*>(g_Ah + (size_t)warp * DIM_K);
        nrm = &g_xsq[warp];
    } else {
        const int row = warp - N;
        src = B + (size_t)row * DIM_K;
        dst = reinterpret_cast<__half2*>(g_Bh + (size_t)row * DIM_K);
        nrm = &g_csq[row];
    }

    float s = 0.0f;
    #pragma unroll
    for (int i = 0; i < 4; i++) {
        float4 v = reinterpret_cast<const float4*>(src)[lane + i * 32];
        dst[2 * (lane + i * 32) + 0] = __floats2half2_rn(v.x, v.y);
        dst[2 * (lane + i * 32) + 1] = __floats2half2_rn(v.z, v.w);
        s += v.x * v.x + v.y * v.y + v.z * v.z + v.w * v.w;
    }
    #pragma unroll
    for (int off = 16; off > 0; off >>= 1)
        s += __shfl_down_sync(0xffffffffu, s, off);
    if (lane == 0) *nrm = s;
}

// ---------------------------------------------------------------------------
// Legacy tensor-core helpers
// ---------------------------------------------------------------------------
__device__ __forceinline__ uint32_t smem_u32(const void* p) {
    uint32_t a;
    asm("{ .reg .u64 t; cvta.to.shared.u64 t, %1; cvt.u32.u64 %0, t; }"
        : "=r"(a) : "l"(p));
    return a;
}

__device__ __forceinline__ void cp_async16(uint32_t dst, const void* src) {
    asm volatile("cp.async.cg.shared.global [%0], [%1], 16;"
                 :: "r"(dst), "l"(src) : "memory");
}

__device__ __forceinline__ void ldsm_x4(uint32_t* r, uint32_t addr) {
    asm volatile("ldmatrix.sync.aligned.m8n8.x4.shared.b16 {%0,%1,%2,%3}, [%4];"
                 : "=r"(r[0]), "=r"(r[1]), "=r"(r[2]), "=r"(r[3]) : "r"(addr));
}

// fp16-accumulator HMMA
__device__ __forceinline__ void mma16816_h(uint32_t* d, const uint32_t* a,
                                           const uint32_t b0, const uint32_t b1) {
    asm volatile(
        "mma.sync.aligned.m16n8k16.row.col.f16.f16.f16.f16 "
        "{%0,%1}, {%2,%3,%4,%5}, {%6,%7}, {%0,%1};"
        : "+r"(d[0]), "+r"(d[1])
        : "r"(a[0]), "r"(a[1]), "r"(a[2]), "r"(a[3]), "r"(b0), "r"(b1));
}

__device__ __forceinline__ void stcs_f2(float* p, float2 v) {
    asm volatile("st.global.cs.v2.f32 [%0], {%1, %2};"
                 :: "l"(p), "f"(v.x), "f"(v.y) : "memory");
}

// SW128 on 128B rows
__device__ __forceinline__ uint32_t swz(int r, int cb) {
    return (uint32_t)(r * 128 + (cb ^ ((r & 7) << 4)));
}

// ---------------------------------------------------------------------------
// GEMM: CTA 128x256, BK=64 halves, 4 stages, 8 warps (warp tile 64x64).
// Register double-buffered fragments + XOR per-kk addressing.
// ---------------------------------------------------------------------------
#define BM 128
#define BN 256
#define BK 64
#define NS (DIM_K / BK)             // 8
#define STAGES 4
#define A_BYTES (BM * 128)
#define B_BYTES (BN * 128)
#define STAGE_BYTES (A_BYTES + B_BYTES)
#define DYN_SMEM (STAGES * STAGE_BYTES + 1024)

__global__ __launch_bounds__(256, 1)
void dist_hmma_kernel(float* __restrict__ C, int M) {
    extern __shared__ char dyn[];
    uint32_t base = (smem_u32(dyn) + 1023u) & ~1023u;

    const int tid  = threadIdx.x;
    const int wid  = tid >> 5;
    const int lane = tid & 31;
    const int rowBase = blockIdx.y * BM;
    const int colBase = blockIdx.x * BN;
    const int wm = (wid & 1) * 64;
    const int wn = (wid >> 1) * 64;

    const __half* gA = g_Ah + (size_t)rowBase * DIM_K;
    const __half* gB = g_Bh + (size_t)colBase * DIM_K;

    uint32_t acc[4][8][2];
    #pragma unroll
    for (int i = 0; i < 4; i++)
        #pragma unroll
        for (int j = 0; j < 8; j++) {
            acc[i][j][0] = 0u;
            acc[i][j][1] = 0u;
        }

    auto load_stage = [&](int ks) {
        const int s = ks & (STAGES - 1);
        const uint32_t sA = base + s * STAGE_BYTES;
        const uint32_t sB = sA + A_BYTES;
        const __half* srcA = gA + ks * BK;
        const __half* srcB = gB + ks * BK;
        #pragma unroll
        for (int i = 0; i < 4; i++) {
            int idx = tid + i * 256;
            int r = idx >> 3, q = idx & 7;
            cp_async16(sA + swz(r, q * 16), srcA + (size_t)r * DIM_K + q * 8);
        }
        #pragma unroll
        for (int i = 0; i < 8; i++) {
            int idx = tid + i * 256;
            int r = idx >> 3, q = idx & 7;
            cp_async16(sB + swz(r, q * 16), srcB + (size_t)r * DIM_K + q * 8);
        }
    };

    #pragma unroll
    for (int s = 0; s < STAGES - 1; s++) {
        load_stage(s);
        asm volatile("cp.async.commit_group;" ::: "memory");
    }

    // per-lane fragment row/col components
    const int fr = (lane & 7) + ((lane >> 3) & 1) * 8;   // row within 16-tile
    const int fc = (lane >> 4) * 16;                     // k8-half byte offset

    // Base LDSM addresses within a stage (stage 0); per-stage add, per-kk XOR.
    // addr(kk) = addr0 ^ (kk << 5)  [SW128: kk only flips bits 5-6, no carries]
    uint32_t aOff[4], bOff[4];
    #pragma unroll
    for (int mi = 0; mi < 4; mi++) aOff[mi] = swz(wm + mi * 16 + fr, fc);
    #pragma unroll
    for (int j = 0; j < 4; j++)  bOff[j] = A_BYTES + swz(wn + j * 16 + fr, fc);

    uint32_t aF[2][4][4], bR[2][4][4];

    for (int ks = 0; ks < NS; ks++) {
        if (ks + STAGES - 1 < NS) load_stage(ks + STAGES - 1);
        asm volatile("cp.async.commit_group;" ::: "memory");
        asm volatile("cp.async.wait_group %0;" :: "n"(STAGES - 1) : "memory");
        __syncthreads();

        const uint32_t sBase = base + (ks & (STAGES - 1)) * STAGE_BYTES;

        // prefetch kk=0 fragments into buffer 0
        #pragma unroll
        for (int mi = 0; mi < 4; mi++) ldsm_x4(aF[0][mi], sBase + aOff[mi]);
        #pragma unroll
        for (int j = 0; j < 4; j++)  ldsm_x4(bR[0][j], sBase + bOff[j]);

        #pragma unroll
        for (int kk = 0; kk < 4; kk++) {
            const int cur = kk & 1;
            if (kk < 3) {
                const uint32_t x = (uint32_t)((kk + 1) << 5);
                #pragma unroll
                for (int mi = 0; mi < 4; mi++)
                    ldsm_x4(aF[cur ^ 1][mi], (sBase + aOff[mi]) ^ x);
                #pragma unroll
                for (int j = 0; j < 4; j++)
                    ldsm_x4(bR[cur ^ 1][j], (sBase + bOff[j]) ^ x);
            }
            #pragma unroll
            for (int mi = 0; mi < 4; mi++) {
                #pragma unroll
                for (int j = 0; j < 4; j++) {
                    mma16816_h(acc[mi][2 * j + 0], aF[cur][mi],
                               bR[cur][j][0], bR[cur][j][2]);
                    mma16816_h(acc[mi][2 * j + 1], aF[cur][mi],
                               bR[cur][j][1], bR[cur][j][3]);
                }
            }
        }
        __syncthreads();
    }

    // ---- epilogue: out = xsq + csq - 2*dot, streaming float2 stores ----
    #pragma unroll
    for (int mi = 0; mi < 4; mi++) {
        const int row0 = rowBase + wm + mi * 16 + (lane >> 2);
        const float xs0 = g_xsq[row0];
        const float xs1 = g_xsq[row0 + 8];
        #pragma unroll
        for (int nj = 0; nj < 8; nj++) {
            const int col0 = colBase + wn + nj * 8 + (lane & 3) * 2;
            const float2 cs = *reinterpret_cast<const float2*>(&g_csq[col0]);
            float2 d0 = __half22float2(*reinterpret_cast<__half2*>(&acc[mi][nj][0]));
            float2 d1 = __half22float2(*reinterpret_cast<__half2*>(&acc[mi][nj][1]));
            float2 o0, o1;
            o0.x = xs0 + cs.x - 2.0f * d0.x;
            o0.y = xs0 + cs.y - 2.0f * d0.y;
            o1.x = xs1 + cs.x - 2.0f * d1.x;
            o1.y = xs1 + cs.y - 2.0f * d1.y;
            stcs_f2(C + (size_t)row0 * M + col0, o0);
            stcs_f2(C + (size_t)(row0 + 8) * M + col0, o1);
        }
    }
}

// ---------------------------------------------------------------------------
extern "C" void kernel_launch(void* const* d_in, const int* in_sizes, int n_in,
                              void* d_out, int out_size) {
    const float* A = (const float*)d_in[0];
    const float* B = (const float*)d_in[1];
    float* C = (float*)d_out;

    int N = in_sizes[0] / DIM_K;              // 16384
    int M = in_sizes[1] / DIM_K;              // 4096

    cudaFuncSetAttribute(dist_hmma_kernel,
                         cudaFuncAttributeMaxDynamicSharedMemorySize, DYN_SMEM);

    int totalWarps = N + M;                   // 20480
    int blocks = (totalWarps * 32 + 255) / 256;
    conv_kernel<<<blocks, 256>>>(A, B, N, M);

    dim3 grid(M / BN, N / BM);                // (16, 128)
    dist_hmma_kernel<<<grid, 256, DYN_SMEM>>>(C, M);
}

// round 14
// speedup vs baseline: 1.8271x; 1.2536x over previous
#include <cuda_runtime.h>
#include <cuda_fp16.h>
#include <cstdint>

#define DIM_K 512
#define NROWS 16384
#define MROWS 4096

// Scratch (no cudaMalloc allowed)
__device__ float g_xsq[NROWS];
__device__ float g_csq[MROWS];
__device__ __half g_Ah[(size_t)NROWS * DIM_K];
__device__ __half g_Bh[(size_t)MROWS * DIM_K];

// ---------------------------------------------------------------------------
// Fused convert(fp32->fp16) + row-norm kernel for BOTH matrices.
// ---------------------------------------------------------------------------
__global__ __launch_bounds__(256)
void conv_kernel(const float* __restrict__ A, const float* __restrict__ B,
                 int N, int M) {
    const int warp = (blockIdx.x * blockDim.x + threadIdx.x) >> 5;
    const int lane = threadIdx.x & 31;
    if (warp >= N + M) return;

    const float* src;
    __half2* dst;
    float* nrm;
    if (warp < N) {
        src = A + (size_t)warp * DIM_K;
        dst = reinterpret_cast<__half2*>(g_Ah + (size_t)warp * DIM_K);
        nrm = &g_xsq[warp];
    } else {
        const int row = warp - N;
        src = B + (size_t)row * DIM_K;
        dst = reinterpret_cast<__half2*>(g_Bh + (size_t)row * DIM_K);
        nrm = &g_csq[row];
    }

    float s = 0.0f;
    #pragma unroll
    for (int i = 0; i < 4; i++) {
        float4 v = reinterpret_cast<const float4*>(src)[lane + i * 32];
        dst[2 * (lane + i * 32) + 0] = __floats2half2_rn(v.x, v.y);
        dst[2 * (lane + i * 32) + 1] = __floats2half2_rn(v.z, v.w);
        s += v.x * v.x + v.y * v.y + v.z * v.z + v.w * v.w;
    }
    #pragma unroll
    for (int off = 16; off > 0; off >>= 1)
        s += __shfl_down_sync(0xffffffffu, s, off);
    if (lane == 0) *nrm = s;
}

// ---------------------------------------------------------------------------
// Legacy tensor-core helpers
// ---------------------------------------------------------------------------
__device__ __forceinline__ uint32_t smem_u32(const void* p) {
    uint32_t a;
    asm("{ .reg .u64 t; cvta.to.shared.u64 t, %1; cvt.u32.u64 %0, t; }"
        : "=r"(a) : "l"(p));
    return a;
}

__device__ __forceinline__ void cp_async16(uint32_t dst, const void* src) {
    asm volatile("cp.async.cg.shared.global [%0], [%1], 16;"
                 :: "r"(dst), "l"(src) : "memory");
}

__device__ __forceinline__ void ldsm_x4(uint32_t* r, uint32_t addr) {
    asm volatile("ldmatrix.sync.aligned.m8n8.x4.shared.b16 {%0,%1,%2,%3}, [%4];"
                 : "=r"(r[0]), "=r"(r[1]), "=r"(r[2]), "=r"(r[3]) : "r"(addr));
}

// fp16-accumulator HMMA
__device__ __forceinline__ void mma16816_h(uint32_t* d, const uint32_t* a,
                                           const uint32_t b0, const uint32_t b1) {
    asm volatile(
        "mma.sync.aligned.m16n8k16.row.col.f16.f16.f16.f16 "
        "{%0,%1}, {%2,%3,%4,%5}, {%6,%7}, {%0,%1};"
        : "+r"(d[0]), "+r"(d[1])
        : "r"(a[0]), "r"(a[1]), "r"(a[2]), "r"(a[3]), "r"(b0), "r"(b1));
}

__device__ __forceinline__ void stcs_f2(float* p, float2 v) {
    asm volatile("st.global.cs.v2.f32 [%0], {%1, %2};"
                 :: "l"(p), "f"(v.x), "f"(v.y) : "memory");
}

// SW128 on 128B rows
__device__ __forceinline__ uint32_t swz(int r, int cb) {
    return (uint32_t)(r * 128 + (cb ^ ((r & 7) << 4)));
}

// ---------------------------------------------------------------------------
// GEMM: CTA 128x256, BK=64 halves, 2 stages, 8 warps (warp tile 64x64),
// 2 CTAs per SM (uncorrelated barrier phases fill each other's tensor gaps).
// ---------------------------------------------------------------------------
#define BM 128
#define BN 256
#define BK 64
#define NS (DIM_K / BK)             // 8
#define STAGES 2
#define A_BYTES (BM * 128)          // 16 KB
#define B_BYTES (BN * 128)          // 32 KB
#define STAGE_BYTES (A_BYTES + B_BYTES)
#define DYN_SMEM (STAGES * STAGE_BYTES + 1024)   // ~97 KB -> 2 CTAs/SM

__global__ __launch_bounds__(256, 2)
void dist_hmma_kernel(float* __restrict__ C, int M) {
    extern __shared__ char dyn[];
    uint32_t base = (smem_u32(dyn) + 1023u) & ~1023u;

    const int tid  = threadIdx.x;
    const int wid  = tid >> 5;
    const int lane = tid & 31;
    const int rowBase = blockIdx.y * BM;
    const int colBase = blockIdx.x * BN;
    const int wm = (wid & 1) * 64;
    const int wn = (wid >> 1) * 64;

    const __half* gA = g_Ah + (size_t)rowBase * DIM_K;
    const __half* gB = g_Bh + (size_t)colBase * DIM_K;

    uint32_t acc[4][8][2];
    #pragma unroll
    for (int i = 0; i < 4; i++)
        #pragma unroll
        for (int j = 0; j < 8; j++) {
            acc[i][j][0] = 0u;
            acc[i][j][1] = 0u;
        }

    auto load_stage = [&](int ks) {
        const int s = ks & (STAGES - 1);
        const uint32_t sA = base + s * STAGE_BYTES;
        const uint32_t sB = sA + A_BYTES;
        const __half* srcA = gA + ks * BK;
        const __half* srcB = gB + ks * BK;
        #pragma unroll
        for (int i = 0; i < 4; i++) {
            int idx = tid + i * 256;
            int r = idx >> 3, q = idx & 7;
            cp_async16(sA + swz(r, q * 16), srcA + (size_t)r * DIM_K + q * 8);
        }
        #pragma unroll
        for (int i = 0; i < 8; i++) {
            int idx = tid + i * 256;
            int r = idx >> 3, q = idx & 7;
            cp_async16(sB + swz(r, q * 16), srcB + (size_t)r * DIM_K + q * 8);
        }
    };

    // prefetch stage 0
    load_stage(0);
    asm volatile("cp.async.commit_group;" ::: "memory");

    // per-lane fragment row/col components
    const int fr = (lane & 7) + ((lane >> 3) & 1) * 8;   // row within 16-tile
    const int fc = (lane >> 4) * 16;                     // k8-half byte offset

    // Base LDSM offsets (stage-relative); per-kk address via XOR (SW128:
    // kk<<5 only flips bits 5-6, no carries).
    uint32_t aOff[4], bOff[4];
    #pragma unroll
    for (int mi = 0; mi < 4; mi++) aOff[mi] = swz(wm + mi * 16 + fr, fc);
    #pragma unroll
    for (int j = 0; j < 4; j++)  bOff[j] = A_BYTES + swz(wn + j * 16 + fr, fc);

    for (int ks = 0; ks < NS; ks++) {
        if (ks + 1 < NS) {
            load_stage(ks + 1);
            asm volatile("cp.async.commit_group;" ::: "memory");
            asm volatile("cp.async.wait_group 1;" ::: "memory");
        } else {
            asm volatile("cp.async.wait_group 0;" ::: "memory");
        }
        __syncthreads();

        const uint32_t sBase = base + (ks & (STAGES - 1)) * STAGE_BYTES;

        #pragma unroll
        for (int kk = 0; kk < 4; kk++) {
            const uint32_t x = (uint32_t)(kk << 5);
            uint32_t aF[4][4], bR[4][4];
            #pragma unroll
            for (int mi = 0; mi < 4; mi++)
                ldsm_x4(aF[mi], (sBase + aOff[mi]) ^ x);
            #pragma unroll
            for (int j = 0; j < 4; j++)
                ldsm_x4(bR[j], (sBase + bOff[j]) ^ x);
            #pragma unroll
            for (int mi = 0; mi < 4; mi++) {
                #pragma unroll
                for (int j = 0; j < 4; j++) {
                    mma16816_h(acc[mi][2 * j + 0], aF[mi], bR[j][0], bR[j][2]);
                    mma16816_h(acc[mi][2 * j + 1], aF[mi], bR[j][1], bR[j][3]);
                }
            }
        }
        __syncthreads();
    }

    // ---- epilogue: out = xsq + csq - 2*dot, streaming float2 stores ----
    #pragma unroll
    for (int mi = 0; mi < 4; mi++) {
        const int row0 = rowBase + wm + mi * 16 + (lane >> 2);
        const float xs0 = g_xsq[row0];
        const float xs1 = g_xsq[row0 + 8];
        #pragma unroll
        for (int nj = 0; nj < 8; nj++) {
            const int col0 = colBase + wn + nj * 8 + (lane & 3) * 2;
            const float2 cs = *reinterpret_cast<const float2*>(&g_csq[col0]);
            float2 d0 = __half22float2(*reinterpret_cast<__half2*>(&acc[mi][nj][0]));
            float2 d1 = __half22float2(*reinterpret_cast<__half2*>(&acc[mi][nj][1]));
            float2 o0, o1;
            o0.x = xs0 + cs.x - 2.0f * d0.x;
            o0.y = xs0 + cs.y - 2.0f * d0.y;
            o1.x = xs1 + cs.x - 2.0f * d1.x;
            o1.y = xs1 + cs.y - 2.0f * d1.y;
            stcs_f2(C + (size_t)row0 * M + col0, o0);
            stcs_f2(C + (size_t)(row0 + 8) * M + col0, o1);
        }
    }
}

// ---------------------------------------------------------------------------
extern "C" void kernel_launch(void* const* d_in, const int* in_sizes, int n_in,
                              void* d_out, int out_size) {
    const float* A = (const float*)d_in[0];
    const float* B = (const float*)d_in[1];
    float* C = (float*)d_out;

    int N = in_sizes[0] / DIM_K;              // 16384
    int M = in_sizes[1] / DIM_K;              // 4096

    cudaFuncSetAttribute(dist_hmma_kernel,
                         cudaFuncAttributeMaxDynamicSharedMemorySize, DYN_SMEM);

    int totalWarps = N + M;                   // 20480
    int blocks = (totalWarps * 32 + 255) / 256;
    conv_kernel<<<blocks, 256>>>(A, B, N, M);

    dim3 grid(M / BN, N / BM);                // (16, 128)
    dist_hmma_kernel<<<grid, 256, DYN_SMEM>>>(C, M);
}

// round 15
// speedup vs baseline: 1.8992x; 1.0395x over previous
#include <cuda_runtime.h>
#include <cuda_fp16.h>
#include <cstdint>

#define DIM_K 512
#define NROWS 16384
#define MROWS 4096

// Scratch (no cudaMalloc allowed)
__device__ float g_xsq[NROWS];
__device__ float g_csq[MROWS];
__device__ __half g_Ah[(size_t)NROWS * DIM_K];
__device__ __half g_Bh[(size_t)MROWS * DIM_K];

// ---------------------------------------------------------------------------
// Fused convert(fp32->fp16) + row-norm kernel for BOTH matrices.
// ---------------------------------------------------------------------------
__global__ __launch_bounds__(256)
void conv_kernel(const float* __restrict__ A, const float* __restrict__ B,
                 int N, int M) {
    const int warp = (blockIdx.x * blockDim.x + threadIdx.x) >> 5;
    const int lane = threadIdx.x & 31;
    if (warp >= N + M) return;

    const float* src;
    __half2* dst;
    float* nrm;
    if (warp < N) {
        src = A + (size_t)warp * DIM_K;
        dst = reinterpret_cast<__half2*>(g_Ah + (size_t)warp * DIM_K);
        nrm = &g_xsq[warp];
    } else {
        const int row = warp - N;
        src = B + (size_t)row * DIM_K;
        dst = reinterpret_cast<__half2*>(g_Bh + (size_t)row * DIM_K);
        nrm = &g_csq[row];
    }

    float s = 0.0f;
    #pragma unroll
    for (int i = 0; i < 4; i++) {
        float4 v = reinterpret_cast<const float4*>(src)[lane + i * 32];
        dst[2 * (lane + i * 32) + 0] = __floats2half2_rn(v.x, v.y);
        dst[2 * (lane + i * 32) + 1] = __floats2half2_rn(v.z, v.w);
        s += v.x * v.x + v.y * v.y + v.z * v.z + v.w * v.w;
    }
    #pragma unroll
    for (int off = 16; off > 0; off >>= 1)
        s += __shfl_down_sync(0xffffffffu, s, off);
    if (lane == 0) *nrm = s;
}

// ---------------------------------------------------------------------------
// Legacy tensor-core helpers
// ---------------------------------------------------------------------------
__device__ __forceinline__ uint32_t smem_u32(const void* p) {
    uint32_t a;
    asm("{ .reg .u64 t; cvta.to.shared.u64 t, %1; cvt.u32.u64 %0, t; }"
        : "=r"(a) : "l"(p));
    return a;
}

// cp.async with literal immediate offsets folded into the address operands
#define CP16_IMM(sreg, preg, SOFF, GOFF)                                      \
    asm volatile("cp.async.cg.shared.global [%0+" SOFF "], [%1+" GOFF "], 16;" \
                 :: "r"(sreg), "l"(preg) : "memory")

__device__ __forceinline__ void ldsm_x4(uint32_t* r, uint32_t addr) {
    asm volatile("ldmatrix.sync.aligned.m8n8.x4.shared.b16 {%0,%1,%2,%3}, [%4];"
                 : "=r"(r[0]), "=r"(r[1]), "=r"(r[2]), "=r"(r[3]) : "r"(addr));
}

// fp16-accumulator HMMA
__device__ __forceinline__ void mma16816_h(uint32_t* d, const uint32_t* a,
                                           const uint32_t b0, const uint32_t b1) {
    asm volatile(
        "mma.sync.aligned.m16n8k16.row.col.f16.f16.f16.f16 "
        "{%0,%1}, {%2,%3,%4,%5}, {%6,%7}, {%0,%1};"
        : "+r"(d[0]), "+r"(d[1])
        : "r"(a[0]), "r"(a[1]), "r"(a[2]), "r"(a[3]), "r"(b0), "r"(b1));
}

__device__ __forceinline__ void stcs_f2(float* p, float2 v) {
    asm volatile("st.global.cs.v2.f32 [%0], {%1, %2};"
                 :: "l"(p), "f"(v.x), "f"(v.y) : "memory");
}

// SW128 on 128B rows
__device__ __forceinline__ uint32_t swz(int r, int cb) {
    return (uint32_t)(r * 128 + (cb ^ ((r & 7) << 4)));
}

// ---------------------------------------------------------------------------
// GEMM: CTA 128x256, BK=64 halves, 2 stages, 8 warps (warp tile 64x64),
// 2 CTAs per SM. Loader addresses are affine in the chunk index -> literal
// immediates; per-slab loader ALU ~5 instructions.
// ---------------------------------------------------------------------------
#define BM 128
#define BN 256
#define BK 64
#define NS (DIM_K / BK)             // 8
#define STAGES 2
#define A_BYTES (BM * 128)          // 16384
#define B_BYTES (BN * 128)          // 32768
#define STAGE_BYTES (A_BYTES + B_BYTES)   // 49152
#define DYN_SMEM (STAGES * STAGE_BYTES + 1024)

__global__ __launch_bounds__(256, 2)
void dist_hmma_kernel(float* __restrict__ C, int M) {
    extern __shared__ char dyn[];
    uint32_t base = (smem_u32(dyn) + 1023u) & ~1023u;

    const int tid  = threadIdx.x;
    const int wid  = tid >> 5;
    const int lane = tid & 31;
    const int rowBase = blockIdx.y * BM;
    const int colBase = blockIdx.x * BN;
    const int wm = (wid & 1) * 64;
    const int wn = (wid >> 1) * 64;

    // ---- loader constants: affine addressing ----
    // idx = tid + i*256 -> r = r0 + 32*i, q fixed. (r & 7) invariant in i.
    const int r0  = tid >> 3;
    const int q16 = (tid & 7) * 16;
    const uint32_t sOff = base + (uint32_t)(r0 * 128 + (q16 ^ ((r0 & 7) << 4)));
    const char* pA = (const char*)(g_Ah + (size_t)rowBase * DIM_K)
                     + r0 * 1024 + q16;
    const char* pB = (const char*)(g_Bh + (size_t)colBase * DIM_K)
                     + r0 * 1024 + q16;

    uint32_t acc[4][8][2];
    #pragma unroll
    for (int i = 0; i < 4; i++)
        #pragma unroll
        for (int j = 0; j < 8; j++) {
            acc[i][j][0] = 0u;
            acc[i][j][1] = 0u;
        }

    auto load_stage = [&](int ks) {
        const uint32_t s = sOff + (uint32_t)(ks & 1) * STAGE_BYTES;
        const char* a = pA + ks * (BK * 2);       // +128 B per slab
        const char* b = pB + ks * (BK * 2);
        // A tile: 4 chunks, stride smem 4096 / global 32768
        CP16_IMM(s, a, "0",     "0");
        CP16_IMM(s, a, "4096",  "32768");
        CP16_IMM(s, a, "8192",  "65536");
        CP16_IMM(s, a, "12288", "98304");
        // B tile: 8 chunks, smem base +A_BYTES(16384), same strides
        CP16_IMM(s, b, "16384", "0");
        CP16_IMM(s, b, "20480", "32768");
        CP16_IMM(s, b, "24576", "65536");
        CP16_IMM(s, b, "28672", "98304");
        CP16_IMM(s, b, "32768", "131072");
        CP16_IMM(s, b, "36864", "163840");
        CP16_IMM(s, b, "40960", "196608");
        CP16_IMM(s, b, "45056", "229376");
    };

    // prefetch stage 0
    load_stage(0);
    asm volatile("cp.async.commit_group;" ::: "memory");

    // per-lane fragment row/col components
    const int fr = (lane & 7) + ((lane >> 3) & 1) * 8;
    const int fc = (lane >> 4) * 16;

    uint32_t aOff[4], bOff[4];
    #pragma unroll
    for (int mi = 0; mi < 4; mi++) aOff[mi] = swz(wm + mi * 16 + fr, fc);
    #pragma unroll
    for (int j = 0; j < 4; j++)  bOff[j] = A_BYTES + swz(wn + j * 16 + fr, fc);

    for (int ks = 0; ks < NS; ks++) {
        if (ks + 1 < NS) {
            load_stage(ks + 1);
            asm volatile("cp.async.commit_group;" ::: "memory");
            asm volatile("cp.async.wait_group 1;" ::: "memory");
        } else {
            asm volatile("cp.async.wait_group 0;" ::: "memory");
        }
        __syncthreads();

        const uint32_t sBase = base + (ks & (STAGES - 1)) * STAGE_BYTES;

        #pragma unroll
        for (int kk = 0; kk < 4; kk++) {
            const uint32_t x = (uint32_t)(kk << 5);   // SW128: flips bits 5-6 only
            uint32_t aF[4][4], bR[4][4];
            #pragma unroll
            for (int mi = 0; mi < 4; mi++)
                ldsm_x4(aF[mi], (sBase + aOff[mi]) ^ x);
            #pragma unroll
            for (int j = 0; j < 4; j++)
                ldsm_x4(bR[j], (sBase + bOff[j]) ^ x);
            #pragma unroll
            for (int mi = 0; mi < 4; mi++) {
                #pragma unroll
                for (int j = 0; j < 4; j++) {
                    mma16816_h(acc[mi][2 * j + 0], aF[mi], bR[j][0], bR[j][2]);
                    mma16816_h(acc[mi][2 * j + 1], aF[mi], bR[j][1], bR[j][3]);
                }
            }
        }
        // Protect stage ks from being overwritten by next slab's cp.async
        // while other warps are still reading it (2-stage ring).
        __syncthreads();
    }

    // ---- epilogue: out = xsq + csq - 2*dot, streaming float2 stores ----
    #pragma unroll
    for (int mi = 0; mi < 4; mi++) {
        const int row0 = rowBase + wm + mi * 16 + (lane >> 2);
        const float xs0 = g_xsq[row0];
        const float xs1 = g_xsq[row0 + 8];
        #pragma unroll
        for (int nj = 0; nj < 8; nj++) {
            const int col0 = colBase + wn + nj * 8 + (lane & 3) * 2;
            const float2 cs = *reinterpret_cast<const float2*>(&g_csq[col0]);
            float2 d0 = __half22float2(*reinterpret_cast<__half2*>(&acc[mi][nj][0]));
            float2 d1 = __half22float2(*reinterpret_cast<__half2*>(&acc[mi][nj][1]));
            float2 o0, o1;
            o0.x = xs0 + cs.x - 2.0f * d0.x;
            o0.y = xs0 + cs.y - 2.0f * d0.y;
            o1.x = xs1 + cs.x - 2.0f * d1.x;
            o1.y = xs1 + cs.y - 2.0f * d1.y;
            stcs_f2(C + (size_t)row0 * M + col0, o0);
            stcs_f2(C + (size_t)(row0 + 8) * M + col0, o1);
        }
    }
}

// ---------------------------------------------------------------------------
extern "C" void kernel_launch(void* const* d_in, const int* in_sizes, int n_in,
                              void* d_out, int out_size) {
    const float* A = (const float*)d_in[0];
    const float* B = (const float*)d_in[1];
    float* C = (float*)d_out;

    int N = in_sizes[0] / DIM_K;              // 16384
    int M = in_sizes[1] / DIM_K;              // 4096

    cudaFuncSetAttribute(dist_hmma_kernel,
                         cudaFuncAttributeMaxDynamicSharedMemorySize, DYN_SMEM);

    int totalWarps = N + M;                   // 20480
    int blocks = (totalWarps * 32 + 255) / 256;
    conv_kernel<<<blocks, 256>>>(A, B, N, M);

    dim3 grid(M / BN, N / BM);                // (16, 128)
    dist_hmma_kernel<<<grid, 256, DYN_SMEM>>>(C, M);
}